// round 4
// baseline (speedup 1.0000x reference)
#include <cuda_runtime.h>
#include <math.h>

#define Bsz 64
#define Tn  12
#define Dd  256
#define Vv  512
#define Ss  512
#define BT  768

// scratch (no allocations allowed)
__device__ float g_gate[2 * BT];          // [0]: mg, [1]: sg (only active slots written)
__device__ float g_gs[Bsz * 2 * Dd];      // graph_state [64, 512]
__device__ float g_h[2 * Bsz * Dd];       // hidden for output MLP (z=0) and feedback MLP (z=1)

__device__ __forceinline__ float gelu_exact(float x) {
    return 0.5f * x * (1.0f + erff(x * 0.70710678118654752440f));
}
__device__ __forceinline__ float sigmoidf_(float x) {
    return 1.0f / (1.0f + expf(-x));
}

// ---------------------------------------------------------------------------
// K1: gate MLPs, computed only for events whose mask fires.
// grid (48, 2), 256 threads. blockIdx.y = gate type (0: map/mg, 1: step/sg).
// ---------------------------------------------------------------------------
__global__ void k_gates(const int* __restrict__ marker, const int* __restrict__ sv,
                        const int* __restrict__ tsv, const int* __restrict__ tvv,
                        const float* __restrict__ evidence,
                        const float* __restrict__ Wmg1, const float* __restrict__ bmg1,
                        const float* __restrict__ Wmg2, const float* __restrict__ bmg2,
                        const float* __restrict__ Wsg1, const float* __restrict__ bsg1,
                        const float* __restrict__ Wsg2, const float* __restrict__ bsg2)
{
    const int g   = blockIdx.y;
    const int tid = threadIdx.x;
    const int NB  = gridDim.x;

    __shared__ int   s_m[BT], s_sv[BT], s_tv[BT];
    __shared__ int   s_jobs[BT];
    __shared__ int   s_njobs;
    __shared__ float xs[4][Dd];
    __shared__ float red[4][8];

    const int* tvp = (g == 0) ? tvv : tsv;
    for (int i = tid; i < BT; i += 256) { s_m[i] = marker[i]; s_sv[i] = sv[i]; s_tv[i] = tvp[i]; }
    __syncthreads();

    // warp 0: compact active jobs via ballot scan
    if (tid < 32) {
        int base = 0;
        for (int c = 0; c < BT / 32; c++) {
            int i = c * 32 + tid;
            int m = s_m[i];
            bool f = (g == 0) ? (((m == 0) || (m == 1)) && (s_sv[i] > 0) && (s_tv[i] > 0))
                              : ((m == 2) && (s_sv[i] > 0) && (s_tv[i] > 0));
            unsigned bal = __ballot_sync(0xffffffffu, f);
            if (f) s_jobs[base + __popc(bal & ((1u << tid) - 1u))] = i;
            base += __popc(bal);
        }
        if (tid == 0) s_njobs = base;
    }
    __syncthreads();
    const int njobs = s_njobs;

    const float* W1 = (g == 0) ? Wmg1 : Wsg1;
    const float* B1 = (g == 0) ? bmg1 : bsg1;
    const float* W2 = (g == 0) ? Wmg2 : Wsg2;
    const float  b2 = (g == 0) ? bmg2[0] : bsg2[0];
    const int lane = tid & 31, wid = tid >> 5;

    for (int j0 = blockIdx.x * 4; j0 < njobs; j0 += NB * 4) {
        int cnt = njobs - j0; if (cnt > 4) cnt = 4;
        #pragma unroll
        for (int q = 0; q < 4; q++) {
            int jj = j0 + (q < cnt ? q : 0);     // clamp to a valid job for padding lanes
            xs[q][tid] = evidence[s_jobs[jj] * Dd + tid];
        }
        __syncthreads();

        float a0 = 0.f, a1 = 0.f, a2 = 0.f, a3 = 0.f;
        #pragma unroll 8
        for (int k = 0; k < Dd; k++) {
            float w = W1[k * Dd + tid];
            a0 += xs[0][k] * w; a1 += xs[1][k] * w;
            a2 += xs[2][k] * w; a3 += xs[3][k] * w;
        }
        float b1v = B1[tid], w2 = W2[tid];
        float h0 = gelu_exact(a0 + b1v) * w2;
        float h1 = gelu_exact(a1 + b1v) * w2;
        float h2 = gelu_exact(a2 + b1v) * w2;
        float h3 = gelu_exact(a3 + b1v) * w2;
        #pragma unroll
        for (int off = 16; off > 0; off >>= 1) {
            h0 += __shfl_down_sync(0xffffffffu, h0, off);
            h1 += __shfl_down_sync(0xffffffffu, h1, off);
            h2 += __shfl_down_sync(0xffffffffu, h2, off);
            h3 += __shfl_down_sync(0xffffffffu, h3, off);
        }
        if (lane == 0) { red[0][wid] = h0; red[1][wid] = h1; red[2][wid] = h2; red[3][wid] = h3; }
        __syncthreads();
        if (tid < cnt) {
            float s = red[tid][0] + red[tid][1] + red[tid][2] + red[tid][3]
                    + red[tid][4] + red[tid][5] + red[tid][6] + red[tid][7];
            g_gate[g * BT + s_jobs[j0 + tid]] = sigmoidf_(s + b2);
        }
        __syncthreads();
    }
}

// ---------------------------------------------------------------------------
// K2: sparse scan + walk readout -> graph_state. one block per batch.
// ---------------------------------------------------------------------------
__global__ void k_walk(const int* __restrict__ marker, const int* __restrict__ srcI,
                       const int* __restrict__ sv,
                       const int* __restrict__ tsymI, const int* __restrict__ tsv,
                       const int* __restrict__ tvalI, const int* __restrict__ tvv,
                       const int* __restrict__ qI, const int* __restrict__ qV,
                       const float* __restrict__ symbol_emb,
                       const float* __restrict__ value_emb)
{
    const int b   = blockIdx.x;
    const int tid = threadIdx.x;

    __shared__ float walk[2][Ss];
    __shared__ float wsum[Ss];
    __shared__ int   wsI[64]; __shared__ float wsW[64];  // <= 1 + 3*12 = 37
    __shared__ int   avI[16]; __shared__ float avW[16];  // <= 12
    __shared__ int   s_nws, s_nav, s_nstep, s_nmap;
    __shared__ int   mS[Tn], mT[Tn]; __shared__ float mW[Tn];
    __shared__ int   sS[Tn], sT[Tn]; __shared__ float sW[Tn];

    for (int i = tid; i < Ss; i += 256) { walk[0][i] = 0.f; wsum[i] = 0.f; }
    __syncthreads();

    if (tid == 0) {
        int nm = 0, ns = 0;
        #pragma unroll
        for (int t = 0; t < Tn; t++) {
            int idx = b * Tn + t;
            int m   = marker[idx];
            int svv = sv[idx];
            int src = srcI[idx]; src = min(max(src, 0), Ss - 1);
            if (((m == 0) || (m == 1)) && svv > 0 && tvv[idx] > 0) {
                int tv = tvalI[idx]; tv = min(max(tv, 0), Vv - 1);
                mS[nm] = src; mT[nm] = tv; mW[nm] = g_gate[idx]; nm++;
            }
            if (m == 2 && svv > 0 && tsv[idx] > 0) {
                int ts = tsymI[idx]; ts = min(max(ts, 0), Ss - 1);
                sS[ns] = src; sT[ns] = ts; sW[ns] = g_gate[BT + idx]; ns++;
            }
        }
        s_nmap = nm; s_nstep = ns;
        int q = qI[b]; q = min(max(q, 0), Ss - 1);
        float qv = (float)qV[b];
        walk[0][q] = qv;
        wsum[q]    = qv;
        wsI[0] = q; wsW[0] = qv;
        s_nws = 1;
    }
    __syncthreads();

    int cur = 0;
    for (int it = 0; it < 3; it++) {
        for (int i = tid; i < Ss; i += 256) walk[cur ^ 1][i] = 0.f;
        __syncthreads();
        if (tid == 0) {
            int ns = s_nstep, nws = s_nws;
            for (int e = 0; e < ns; e++) {
                float v = walk[cur][sS[e]];
                if (v != 0.f) {
                    float c = v * sW[e];
                    walk[cur ^ 1][sT[e]] += c;
                    wsum[sT[e]] += c;
                    wsI[nws] = sT[e]; wsW[nws] = c; nws++;
                }
            }
            s_nws = nws;
        }
        __syncthreads();
        cur ^= 1;
    }

    if (tid == 0) {
        int na = 0;
        for (int e = 0; e < s_nmap; e++) {
            float v = wsum[mS[e]];
            if (v != 0.f) { avI[na] = mT[e]; avW[na] = v * mW[e]; na++; }
        }
        s_nav = na;
    }
    __syncthreads();

    // gather: acc_s = sum_p w_p * symbol_emb[idx_p], acc_v@value_emb analogous
    const int d = tid;              // 256 threads == Dd
    const int nws = s_nws, nav = s_nav;
    float ss = 0.f;
    for (int p = 0; p < nws; p++) ss += wsW[p] * symbol_emb[wsI[p] * Dd + d];
    float vv = 0.f;
    for (int p = 0; p < nav; p++) vv += avW[p] * value_emb[avI[p] * Dd + d];
    g_gs[b * (2 * Dd) + d]      = ss;
    g_gs[b * (2 * Dd) + Dd + d] = vv;
}

// ---------------------------------------------------------------------------
// K3a: h = gelu(gs @ W1 + b1) for both MLPs. grid (8, 4, 2), 256 threads.
// ---------------------------------------------------------------------------
__global__ void k_hidden(const float* __restrict__ Wo1, const float* __restrict__ bo1,
                         const float* __restrict__ Wf1, const float* __restrict__ bf1)
{
    const int z  = blockIdx.z;
    const float* W1 = (z == 0) ? Wo1 : Wf1;
    const float* B1 = (z == 0) ? bo1 : bf1;
    float* hout = g_h + z * Bsz * Dd;

    const int tid = threadIdx.x;
    const int c = tid & 31, rr = tid >> 5;
    const int col  = blockIdx.x * 32 + c;
    const int row0 = blockIdx.y * 16;

    __shared__ float gsS[16 * 512];
    for (int i = tid; i < 16 * 512; i += 256) gsS[i] = g_gs[row0 * 512 + i];
    __syncthreads();

    float a0 = 0.f, a1 = 0.f;
    const float* g0 = gsS + rr * 512;
    const float* g1 = gsS + (rr + 8) * 512;
    #pragma unroll 8
    for (int k = 0; k < 512; k++) {
        float w = W1[k * Dd + col];
        a0 += g0[k] * w;
        a1 += g1[k] * w;
    }
    float bb = B1[col];
    hout[(row0 + rr)     * Dd + col] = gelu_exact(a0 + bb);
    hout[(row0 + rr + 8) * Dd + col] = gelu_exact(a1 + bb);
}

// ---------------------------------------------------------------------------
// K3b: out = h @ W2 + b2.  z=0: logits [64,512] -> d_out[0:32768]
//                          z=1: feedback [64,256] -> d_out[32768:49152]
// grid (16, 4, 2), 256 threads (z=1 blocks with x>=8 exit).
// ---------------------------------------------------------------------------
__global__ void k_out(const float* __restrict__ Wo2, const float* __restrict__ bo2,
                      const float* __restrict__ Wf2, const float* __restrict__ bf2,
                      float* __restrict__ out)
{
    const int z  = blockIdx.z;
    const int OW = (z == 0) ? Vv : Dd;
    if ((int)blockIdx.x * 32 >= OW) return;
    const float* W2 = (z == 0) ? Wo2 : Wf2;
    const float* B2 = (z == 0) ? bo2 : bf2;
    const float* hin = g_h + z * Bsz * Dd;
    float* obase = (z == 0) ? out : out + Bsz * Vv;

    const int tid = threadIdx.x;
    const int c = tid & 31, rr = tid >> 5;
    const int col  = blockIdx.x * 32 + c;
    const int row0 = blockIdx.y * 16;

    __shared__ float hS[16 * 256];
    for (int i = tid; i < 16 * 256; i += 256) hS[i] = hin[row0 * 256 + i];
    __syncthreads();

    float a0 = 0.f, a1 = 0.f;
    const float* h0 = hS + rr * 256;
    const float* h1 = hS + (rr + 8) * 256;
    #pragma unroll 8
    for (int k = 0; k < 256; k++) {
        float w = W2[k * OW + col];
        a0 += h0[k] * w;
        a1 += h1[k] * w;
    }
    float bb = B2[col];
    obase[(row0 + rr)     * OW + col] = a0 + bb;
    obase[(row0 + rr + 8) * OW + col] = a1 + bb;
}

// ---------------------------------------------------------------------------
extern "C" void kernel_launch(void* const* d_in, const int* in_sizes, int n_in,
                              void* d_out, int out_size)
{
    const int*   marker     = (const int*)d_in[0];
    const int*   srcI       = (const int*)d_in[1];
    const int*   sv         = (const int*)d_in[2];
    const int*   tsymI      = (const int*)d_in[3];
    const int*   tsv        = (const int*)d_in[4];
    const int*   tvalI      = (const int*)d_in[5];
    const int*   tvv        = (const int*)d_in[6];
    const int*   qI         = (const int*)d_in[7];
    const int*   qV         = (const int*)d_in[8];
    const float* evidence   = (const float*)d_in[9];
    const float* symbol_emb = (const float*)d_in[10];
    const float* value_emb  = (const float*)d_in[11];
    const float* Wmg1 = (const float*)d_in[12]; const float* bmg1 = (const float*)d_in[13];
    const float* Wmg2 = (const float*)d_in[14]; const float* bmg2 = (const float*)d_in[15];
    const float* Wsg1 = (const float*)d_in[16]; const float* bsg1 = (const float*)d_in[17];
    const float* Wsg2 = (const float*)d_in[18]; const float* bsg2 = (const float*)d_in[19];
    const float* Wf1  = (const float*)d_in[20]; const float* bf1  = (const float*)d_in[21];
    const float* Wf2  = (const float*)d_in[22]; const float* bf2  = (const float*)d_in[23];
    const float* Wo1  = (const float*)d_in[24]; const float* bo1  = (const float*)d_in[25];
    const float* Wo2  = (const float*)d_in[26]; const float* bo2  = (const float*)d_in[27];
    float* out = (float*)d_out;

    k_gates<<<dim3(48, 2, 1), 256>>>(marker, sv, tsv, tvv, evidence,
                                     Wmg1, bmg1, Wmg2, bmg2, Wsg1, bsg1, Wsg2, bsg2);
    k_walk<<<Bsz, 256>>>(marker, srcI, sv, tsymI, tsv, tvalI, tvv, qI, qV,
                         symbol_emb, value_emb);
    k_hidden<<<dim3(8, 4, 2), 256>>>(Wo1, bo1, Wf1, bf1);
    k_out<<<dim3(16, 4, 2), 256>>>(Wo2, bo2, Wf2, bf2, out);
}

// round 5
// speedup vs baseline: 1.7193x; 1.7193x over previous
#include <cuda_runtime.h>
#include <math.h>

#define Bsz 64
#define Tn  12
#define Dd  256
#define Vv  512
#define Ss  512
#define BT  768

// scratch (no allocations allowed)
__device__ float g_gate[2 * BT];                     // [0]: mg, [1]: sg (active slots only)
__device__ float g_gs[Bsz * 2 * Dd];                 // graph_state [64, 512]
__device__ __align__(16) float g_hp[8 * 2 * Bsz * Dd]; // hidden partials [ks][z][64][256]
__device__ __align__(16) float g_h[2 * Bsz * Dd];    // gelu'd hidden [z][64][256]

__device__ __forceinline__ float gelu_exact(float x) {
    return 0.5f * x * (1.0f + erff(x * 0.70710678118654752440f));
}
__device__ __forceinline__ float sigmoidf_(float x) {
    return 1.0f / (1.0f + expf(-x));
}

// ---------------------------------------------------------------------------
// K1: gate MLPs for active events only. grid (32, 2), 256 thr.
// blockIdx.y = gate type (0: map/mg, 1: step/sg). 4 jobs per block pass.
// Within block: warp w -> (kq = w>>1 in 0..3 : 64-k chunk, cg = w&1 : 128 cols).
// ---------------------------------------------------------------------------
__global__ void __launch_bounds__(256)
k_gates(const int* __restrict__ marker, const int* __restrict__ sv,
        const int* __restrict__ tsv, const int* __restrict__ tvv,
        const float* __restrict__ evidence,
        const float* __restrict__ Wmg1, const float* __restrict__ bmg1,
        const float* __restrict__ Wmg2, const float* __restrict__ bmg2,
        const float* __restrict__ Wsg1, const float* __restrict__ bsg1,
        const float* __restrict__ Wsg2, const float* __restrict__ bsg2)
{
    const int g   = blockIdx.y;
    const int tid = threadIdx.x;
    const int NB  = gridDim.x;

    __shared__ int   s_m[BT], s_sv[BT], s_tv[BT];
    __shared__ int   s_jobs[BT];
    __shared__ int   s_njobs;
    __shared__ __align__(16) float xs[4][Dd];
    __shared__ __align__(16) float s_part[4][4][Dd];   // [kq][job][col]
    __shared__ float red[4][8];

    const int* tvp = (g == 0) ? tvv : tsv;
    for (int i = tid; i < BT; i += 256) { s_m[i] = marker[i]; s_sv[i] = sv[i]; s_tv[i] = tvp[i]; }
    __syncthreads();

    // warp 0: compact active jobs via ballot scan
    if (tid < 32) {
        int base = 0;
        for (int c = 0; c < BT / 32; c++) {
            int i = c * 32 + tid;
            int m = s_m[i];
            bool f = (g == 0) ? (((m == 0) || (m == 1)) && (s_sv[i] > 0) && (s_tv[i] > 0))
                              : ((m == 2) && (s_sv[i] > 0) && (s_tv[i] > 0));
            unsigned bal = __ballot_sync(0xffffffffu, f);
            if (f) s_jobs[base + __popc(bal & ((1u << tid) - 1u))] = i;
            base += __popc(bal);
        }
        if (tid == 0) s_njobs = base;
    }
    __syncthreads();
    const int njobs = s_njobs;

    const float* W1 = (g == 0) ? Wmg1 : Wsg1;
    const float* B1 = (g == 0) ? bmg1 : bsg1;
    const float* W2 = (g == 0) ? Wmg2 : Wsg2;
    const float  b2 = (g == 0) ? bmg2[0] : bsg2[0];

    const int lane = tid & 31, w = tid >> 5;
    const int cg = w & 1, kq = w >> 1;
    const int colb = cg * 128 + lane * 4;

    for (int j0 = blockIdx.x * 4; j0 < njobs; j0 += NB * 4) {
        int cnt = njobs - j0; if (cnt > 4) cnt = 4;
        #pragma unroll
        for (int q = 0; q < 4; q++) {
            int jj = j0 + (q < cnt ? q : 0);       // clamp: padded lanes recompute job 0
            xs[q][tid] = evidence[s_jobs[jj] * Dd + tid];
        }
        __syncthreads();

        float4 a0 = {0,0,0,0}, a1 = {0,0,0,0}, a2 = {0,0,0,0}, a3 = {0,0,0,0};
        const float* Wp = W1 + (kq * 64) * Dd + colb;
        #pragma unroll 8
        for (int kk = 0; kk < 64; kk++) {
            float4 wv = *(const float4*)(Wp + kk * Dd);
            int k = kq * 64 + kk;
            float x0 = xs[0][k], x1 = xs[1][k], x2 = xs[2][k], x3 = xs[3][k];
            a0.x += x0*wv.x; a0.y += x0*wv.y; a0.z += x0*wv.z; a0.w += x0*wv.w;
            a1.x += x1*wv.x; a1.y += x1*wv.y; a1.z += x1*wv.z; a1.w += x1*wv.w;
            a2.x += x2*wv.x; a2.y += x2*wv.y; a2.z += x2*wv.z; a2.w += x2*wv.w;
            a3.x += x3*wv.x; a3.y += x3*wv.y; a3.z += x3*wv.z; a3.w += x3*wv.w;
        }
        *(float4*)&s_part[kq][0][colb] = a0;
        *(float4*)&s_part[kq][1][colb] = a1;
        *(float4*)&s_part[kq][2][colb] = a2;
        *(float4*)&s_part[kq][3][colb] = a3;
        __syncthreads();

        // thread = hidden col; sum 4 k-chunks, gelu, *W2
        float b1v = B1[tid], w2v = W2[tid];
        float h0 = gelu_exact(s_part[0][0][tid] + s_part[1][0][tid] + s_part[2][0][tid] + s_part[3][0][tid] + b1v) * w2v;
        float h1 = gelu_exact(s_part[0][1][tid] + s_part[1][1][tid] + s_part[2][1][tid] + s_part[3][1][tid] + b1v) * w2v;
        float h2 = gelu_exact(s_part[0][2][tid] + s_part[1][2][tid] + s_part[2][2][tid] + s_part[3][2][tid] + b1v) * w2v;
        float h3 = gelu_exact(s_part[0][3][tid] + s_part[1][3][tid] + s_part[2][3][tid] + s_part[3][3][tid] + b1v) * w2v;
        #pragma unroll
        for (int off = 16; off > 0; off >>= 1) {
            h0 += __shfl_down_sync(0xffffffffu, h0, off);
            h1 += __shfl_down_sync(0xffffffffu, h1, off);
            h2 += __shfl_down_sync(0xffffffffu, h2, off);
            h3 += __shfl_down_sync(0xffffffffu, h3, off);
        }
        if (lane == 0) { red[0][w] = h0; red[1][w] = h1; red[2][w] = h2; red[3][w] = h3; }
        __syncthreads();
        if (tid < cnt) {
            float s = red[tid][0] + red[tid][1] + red[tid][2] + red[tid][3]
                    + red[tid][4] + red[tid][5] + red[tid][6] + red[tid][7];
            g_gate[g * BT + s_jobs[j0 + tid]] = sigmoidf_(s + b2);
        }
        __syncthreads();
    }
}

// ---------------------------------------------------------------------------
// K2: sparse scan + walk readout -> graph_state. one block per batch.
// ---------------------------------------------------------------------------
__global__ void __launch_bounds__(256)
k_walk(const int* __restrict__ marker, const int* __restrict__ srcI,
       const int* __restrict__ sv,
       const int* __restrict__ tsymI, const int* __restrict__ tsv,
       const int* __restrict__ tvalI, const int* __restrict__ tvv,
       const int* __restrict__ qI, const int* __restrict__ qV,
       const float* __restrict__ symbol_emb,
       const float* __restrict__ value_emb)
{
    const int b   = blockIdx.x;
    const int tid = threadIdx.x;

    __shared__ float walk[2][Ss];
    __shared__ float wsum[Ss];
    __shared__ int   wsI[64]; __shared__ float wsW[64];  // <= 1 + 3*12 = 37
    __shared__ int   avI[16]; __shared__ float avW[16];  // <= 12
    __shared__ int   s_nws, s_nav, s_nstep, s_nmap;
    __shared__ int   mS[Tn], mT[Tn]; __shared__ float mW[Tn];
    __shared__ int   sS[Tn], sT[Tn]; __shared__ float sW[Tn];
    // parallel-staged event fields
    __shared__ int   e_m[Tn], e_src[Tn], e_sv[Tn], e_ts[Tn], e_tsv[Tn], e_tv[Tn], e_tvv[Tn];
    __shared__ float e_mg[Tn], e_sg[Tn];
    __shared__ int   e_q, e_qv;

    for (int i = tid; i < Ss; i += 256) { walk[0][i] = 0.f; wsum[i] = 0.f; }
    if (tid < Tn) {
        int idx = b * Tn + tid;
        e_m[tid]   = marker[idx];
        e_src[tid] = srcI[idx];
        e_sv[tid]  = sv[idx];
        e_ts[tid]  = tsymI[idx];
        e_tsv[tid] = tsv[idx];
        e_tv[tid]  = tvalI[idx];
        e_tvv[tid] = tvv[idx];
        e_mg[tid]  = g_gate[idx];
        e_sg[tid]  = g_gate[BT + idx];
    }
    if (tid == Tn) { e_q = qI[b]; e_qv = qV[b]; }
    __syncthreads();

    if (tid == 0) {
        int nm = 0, ns = 0;
        #pragma unroll
        for (int t = 0; t < Tn; t++) {
            int m   = e_m[t];
            int svv = e_sv[t];
            int src = e_src[t]; src = min(max(src, 0), Ss - 1);
            if (((m == 0) || (m == 1)) && svv > 0 && e_tvv[t] > 0) {
                int tv = e_tv[t]; tv = min(max(tv, 0), Vv - 1);
                mS[nm] = src; mT[nm] = tv; mW[nm] = e_mg[t]; nm++;
            }
            if (m == 2 && svv > 0 && e_tsv[t] > 0) {
                int ts = e_ts[t]; ts = min(max(ts, 0), Ss - 1);
                sS[ns] = src; sT[ns] = ts; sW[ns] = e_sg[t]; ns++;
            }
        }
        s_nmap = nm; s_nstep = ns;
        int q = e_q; q = min(max(q, 0), Ss - 1);
        float qv = (float)e_qv;
        walk[0][q] = qv;
        wsum[q]    = qv;
        wsI[0] = q; wsW[0] = qv;
        s_nws = 1;
    }
    __syncthreads();

    int cur = 0;
    for (int it = 0; it < 3; it++) {
        for (int i = tid; i < Ss; i += 256) walk[cur ^ 1][i] = 0.f;
        __syncthreads();
        if (tid == 0) {
            int ns = s_nstep, nws = s_nws;
            for (int e = 0; e < ns; e++) {
                float v = walk[cur][sS[e]];
                if (v != 0.f) {
                    float c = v * sW[e];
                    walk[cur ^ 1][sT[e]] += c;
                    wsum[sT[e]] += c;
                    wsI[nws] = sT[e]; wsW[nws] = c; nws++;
                }
            }
            s_nws = nws;
        }
        __syncthreads();
        cur ^= 1;
    }

    if (tid == 0) {
        int na = 0;
        for (int e = 0; e < s_nmap; e++) {
            float v = wsum[mS[e]];
            if (v != 0.f) { avI[na] = mT[e]; avW[na] = v * mW[e]; na++; }
        }
        s_nav = na;
    }
    __syncthreads();

    // gather: acc_s = sum_p w_p * symbol_emb[idx_p]; acc_v@value_emb analogous
    const int d = tid;              // 256 threads == Dd
    const int nws = s_nws, nav = s_nav;
    float ss = 0.f;
    for (int p = 0; p < nws; p++) ss += wsW[p] * symbol_emb[wsI[p] * Dd + d];
    float vv = 0.f;
    for (int p = 0; p < nav; p++) vv += avW[p] * value_emb[avI[p] * Dd + d];
    g_gs[b * (2 * Dd) + d]      = ss;
    g_gs[b * (2 * Dd) + Dd + d] = vv;
}

// ---------------------------------------------------------------------------
// K3: hidden partials, split-K=8.  grid (2 coltiles, 4 rowtiles, 16 = z*8+ks).
// thread: 4 cols (float4 W) x 2 rows. Writes raw partial, no bias/gelu.
// ---------------------------------------------------------------------------
__global__ void __launch_bounds__(256)
k_hidden(const float* __restrict__ Wo1, const float* __restrict__ Wf1)
{
    const int zks = blockIdx.z;
    const int z = zks >> 3, ks = zks & 7;
    const float* W1 = z ? Wf1 : Wo1;
    const int rowt = blockIdx.y, colt = blockIdx.x;

    const int tid = threadIdx.x;
    const int lane = tid & 31, rr = tid >> 5;

    __shared__ float gsS[16][64];
    for (int i = tid; i < 1024; i += 256) {
        int r = i >> 6, kk = i & 63;
        gsS[r][kk] = g_gs[(rowt * 16 + r) * 512 + ks * 64 + kk];
    }
    __syncthreads();

    const int col = colt * 128 + lane * 4;
    const float* Wp = W1 + (ks * 64) * Dd + col;
    float4 a0 = {0,0,0,0}, a1 = {0,0,0,0};
    #pragma unroll 8
    for (int kk = 0; kk < 64; kk++) {
        float4 wv = *(const float4*)(Wp + kk * Dd);
        float x0 = gsS[rr][kk], x1 = gsS[rr + 8][kk];
        a0.x += x0*wv.x; a0.y += x0*wv.y; a0.z += x0*wv.z; a0.w += x0*wv.w;
        a1.x += x1*wv.x; a1.y += x1*wv.y; a1.z += x1*wv.z; a1.w += x1*wv.w;
    }
    const int base = ((ks * 2 + z) * Bsz) * Dd;
    const int r0 = rowt * 16 + rr;
    *(float4*)&g_hp[base + r0 * Dd + col]       = a0;
    *(float4*)&g_hp[base + (r0 + 8) * Dd + col] = a1;
}

// ---------------------------------------------------------------------------
// K4: fixup — h = gelu(sum_ks partials + b1); also init out with output biases.
// grid (128, 1, 1), 256 thr -> 32768 threads.
// ---------------------------------------------------------------------------
__global__ void __launch_bounds__(256)
k_fix(const float* __restrict__ bo1, const float* __restrict__ bf1,
      const float* __restrict__ bo2, const float* __restrict__ bf2,
      float* __restrict__ out)
{
    const int i = blockIdx.x * 256 + threadIdx.x;   // 0..32767
    {   // hidden sum + gelu
        const int z = i >> 14, rc = i & 16383, c = i & 255;
        float s = 0.f;
        #pragma unroll
        for (int ks = 0; ks < 8; ks++) s += g_hp[((ks * 2 + z) << 14) + rc];
        float b = z ? bf1[c] : bo1[c];
        g_h[i] = gelu_exact(s + b);
    }
    // bias-init outputs (logits then feedback)
    out[i] = bo2[i & 511];
    if (i < 16384) out[32768 + i] = bf2[i & 255];
}

// ---------------------------------------------------------------------------
// K5: out partials via atomicAdd into bias-initialized d_out. split-K=4.
// grid (4 coltiles, 4 rowtiles, 8 = z*4+ks). z=1 coltiles>=2 exit.
// ---------------------------------------------------------------------------
__global__ void __launch_bounds__(256)
k_out(const float* __restrict__ Wo2, const float* __restrict__ Wf2,
      float* __restrict__ out)
{
    const int z4 = blockIdx.z;
    const int z = z4 >> 2, ks = z4 & 3;
    const int OW = z ? Dd : Vv;
    const int colt = blockIdx.x;
    if (colt * 128 >= OW) return;
    const float* W2 = z ? Wf2 : Wo2;
    const int rowt = blockIdx.y;

    const int tid = threadIdx.x;
    const int lane = tid & 31, rr = tid >> 5;

    __shared__ float hS[16][64];
    for (int i = tid; i < 1024; i += 256) {
        int r = i >> 6, kk = i & 63;
        hS[r][kk] = g_h[(z * Bsz + rowt * 16 + r) * Dd + ks * 64 + kk];
    }
    __syncthreads();

    const int col = colt * 128 + lane * 4;
    const float* Wp = W2 + (ks * 64) * OW + col;
    float4 a0 = {0,0,0,0}, a1 = {0,0,0,0};
    #pragma unroll 8
    for (int kk = 0; kk < 64; kk++) {
        float4 wv = *(const float4*)(Wp + kk * OW);
        float x0 = hS[rr][kk], x1 = hS[rr + 8][kk];
        a0.x += x0*wv.x; a0.y += x0*wv.y; a0.z += x0*wv.z; a0.w += x0*wv.w;
        a1.x += x1*wv.x; a1.y += x1*wv.y; a1.z += x1*wv.z; a1.w += x1*wv.w;
    }
    float* ob = z ? (out + Bsz * Vv) : out;
    const int r0 = rowt * 16 + rr;
    float* p0 = ob + r0 * OW + col;
    float* p1 = ob + (r0 + 8) * OW + col;
    atomicAdd(p0 + 0, a0.x); atomicAdd(p0 + 1, a0.y);
    atomicAdd(p0 + 2, a0.z); atomicAdd(p0 + 3, a0.w);
    atomicAdd(p1 + 0, a1.x); atomicAdd(p1 + 1, a1.y);
    atomicAdd(p1 + 2, a1.z); atomicAdd(p1 + 3, a1.w);
}

// ---------------------------------------------------------------------------
extern "C" void kernel_launch(void* const* d_in, const int* in_sizes, int n_in,
                              void* d_out, int out_size)
{
    const int*   marker     = (const int*)d_in[0];
    const int*   srcI       = (const int*)d_in[1];
    const int*   sv         = (const int*)d_in[2];
    const int*   tsymI      = (const int*)d_in[3];
    const int*   tsv        = (const int*)d_in[4];
    const int*   tvalI      = (const int*)d_in[5];
    const int*   tvv        = (const int*)d_in[6];
    const int*   qI         = (const int*)d_in[7];
    const int*   qV         = (const int*)d_in[8];
    const float* evidence   = (const float*)d_in[9];
    const float* symbol_emb = (const float*)d_in[10];
    const float* value_emb  = (const float*)d_in[11];
    const float* Wmg1 = (const float*)d_in[12]; const float* bmg1 = (const float*)d_in[13];
    const float* Wmg2 = (const float*)d_in[14]; const float* bmg2 = (const float*)d_in[15];
    const float* Wsg1 = (const float*)d_in[16]; const float* bsg1 = (const float*)d_in[17];
    const float* Wsg2 = (const float*)d_in[18]; const float* bsg2 = (const float*)d_in[19];
    const float* Wf1  = (const float*)d_in[20]; const float* bf1  = (const float*)d_in[21];
    const float* Wf2  = (const float*)d_in[22]; const float* bf2  = (const float*)d_in[23];
    const float* Wo1  = (const float*)d_in[24]; const float* bo1  = (const float*)d_in[25];
    const float* Wo2  = (const float*)d_in[26]; const float* bo2  = (const float*)d_in[27];
    float* out = (float*)d_out;

    k_gates<<<dim3(32, 2, 1), 256>>>(marker, sv, tsv, tvv, evidence,
                                     Wmg1, bmg1, Wmg2, bmg2, Wsg1, bsg1, Wsg2, bsg2);
    k_walk<<<Bsz, 256>>>(marker, srcI, sv, tsymI, tsv, tvalI, tvv, qI, qV,
                         symbol_emb, value_emb);
    k_hidden<<<dim3(2, 4, 16), 256>>>(Wo1, Wf1);
    k_fix<<<128, 256>>>(bo1, bf1, bo2, bf2, out);
    k_out<<<dim3(4, 4, 8), 256>>>(Wo2, Wf2, out);
}

// round 6
// speedup vs baseline: 2.0162x; 1.1727x over previous
#include <cuda_runtime.h>
#include <math.h>

#define Bsz 64
#define Tn  12
#define Dd  256
#define Vv  512
#define Ss  512
#define BT  768

// scratch (no allocations allowed)
__device__ float g_gs[Bsz * 2 * Dd];                   // graph_state [64, 512]
__device__ __align__(16) float g_hp[8 * 2 * Bsz * Dd]; // hidden partials [ks][z][64][256]

__device__ __forceinline__ float gelu_exact(float x) {
    return 0.5f * x * (1.0f + erff(x * 0.70710678118654752440f));
}
__device__ __forceinline__ float sigmoidf_(float x) {
    return 1.0f / (1.0f + expf(-x));
}

// ---------------------------------------------------------------------------
// K1: fused gates + walk, one block per batch. Also bias-initializes d_out.
// ---------------------------------------------------------------------------
__global__ void __launch_bounds__(256)
k_gw(const int* __restrict__ marker, const int* __restrict__ srcI,
     const int* __restrict__ sv,
     const int* __restrict__ tsymI, const int* __restrict__ tsv,
     const int* __restrict__ tvalI, const int* __restrict__ tvv,
     const int* __restrict__ qI, const int* __restrict__ qV,
     const float* __restrict__ evidence,
     const float* __restrict__ symbol_emb, const float* __restrict__ value_emb,
     const float* __restrict__ Wmg1, const float* __restrict__ bmg1,
     const float* __restrict__ Wmg2, const float* __restrict__ bmg2,
     const float* __restrict__ Wsg1, const float* __restrict__ bsg1,
     const float* __restrict__ Wsg2, const float* __restrict__ bsg2,
     const float* __restrict__ bo2, const float* __restrict__ bf2,
     float* __restrict__ out)
{
    const int b   = blockIdx.x;
    const int tid = threadIdx.x;

    // bias-init output (depends on nothing; k_out atomicAdds on top of this)
    #pragma unroll
    for (int j = tid; j < BT; j += 256) {
        int i = b * BT + j;                       // 64*768 = 49152 = out_size
        out[i] = (i < Bsz * Vv) ? bo2[i & (Vv - 1)] : bf2[i & (Dd - 1)];
    }

    __shared__ int   e_m[Tn], e_src[Tn], e_sv[Tn], e_ts[Tn], e_tsv[Tn], e_tv[Tn], e_tvv[Tn];
    __shared__ int   e_q, e_qv;
    __shared__ int   jobT[2][Tn];
    __shared__ int   nJob[2];
    __shared__ float gateV[2][Tn];
    __shared__ __align__(16) float xs[4][Dd];
    __shared__ __align__(16) float s_part[4][4][Dd];   // [kq][job][col]
    __shared__ float red[4][8];

    __shared__ float walk[2][Ss];
    __shared__ float wsum[Ss];
    __shared__ int   wsI[64]; __shared__ float wsW[64];  // <= 1 + 3*12 = 37
    __shared__ int   avI[16]; __shared__ float avW[16];  // <= 12
    __shared__ int   s_nws, s_nav;
    __shared__ int   mS[Tn], mT[Tn]; __shared__ float mW[Tn];
    __shared__ int   sS[Tn], sT[Tn]; __shared__ float sW[Tn];

    for (int i = tid; i < Ss; i += 256) { walk[0][i] = 0.f; wsum[i] = 0.f; }
    if (tid < Tn) {
        int idx = b * Tn + tid;
        e_m[tid]   = marker[idx];
        e_src[tid] = srcI[idx];
        e_sv[tid]  = sv[idx];
        e_ts[tid]  = tsymI[idx];
        e_tsv[tid] = tsv[idx];
        e_tv[tid]  = tvalI[idx];
        e_tvv[tid] = tvv[idx];
    }
    if (tid == Tn) { e_q = qI[b]; e_qv = qV[b]; }
    __syncthreads();

    // build job lists (map gate jobs / step gate jobs)
    if (tid == 0) {
        int nm = 0, ns = 0;
        #pragma unroll
        for (int t = 0; t < Tn; t++) {
            int m = e_m[t];
            bool svv = e_sv[t] > 0;
            if (((m == 0) || (m == 1)) && svv && e_tvv[t] > 0) jobT[0][nm++] = t;
            if (m == 2 && svv && e_tsv[t] > 0)                 jobT[1][ns++] = t;
        }
        nJob[0] = nm; nJob[1] = ns;
    }
    __syncthreads();

    // gate MLPs, 4 jobs per pass, k-split across warps
    const int lane = tid & 31, w = tid >> 5;
    const int cg = w & 1, kq = w >> 1;
    const int colb = cg * 128 + lane * 4;

    for (int g = 0; g < 2; g++) {
        const float* W1 = g ? Wsg1 : Wmg1;
        const float* B1 = g ? bsg1 : bmg1;
        const float* W2 = g ? Wsg2 : Wmg2;
        const float  b2 = g ? bsg2[0] : bmg2[0];
        const int nj = nJob[g];

        for (int j0 = 0; j0 < nj; j0 += 4) {
            int cnt = nj - j0; if (cnt > 4) cnt = 4;
            #pragma unroll
            for (int q = 0; q < 4; q++) {
                int t = jobT[g][j0 + (q < cnt ? q : 0)];  // padded lanes redo a valid job
                xs[q][tid] = evidence[(b * Tn + t) * Dd + tid];
            }
            __syncthreads();

            float4 a0 = {0,0,0,0}, a1 = {0,0,0,0}, a2 = {0,0,0,0}, a3 = {0,0,0,0};
            const float* Wp = W1 + (kq * 64) * Dd + colb;
            #pragma unroll 8
            for (int kk = 0; kk < 64; kk++) {
                float4 wv = *(const float4*)(Wp + kk * Dd);
                int k = kq * 64 + kk;
                float x0 = xs[0][k], x1 = xs[1][k], x2 = xs[2][k], x3 = xs[3][k];
                a0.x += x0*wv.x; a0.y += x0*wv.y; a0.z += x0*wv.z; a0.w += x0*wv.w;
                a1.x += x1*wv.x; a1.y += x1*wv.y; a1.z += x1*wv.z; a1.w += x1*wv.w;
                a2.x += x2*wv.x; a2.y += x2*wv.y; a2.z += x2*wv.z; a2.w += x2*wv.w;
                a3.x += x3*wv.x; a3.y += x3*wv.y; a3.z += x3*wv.z; a3.w += x3*wv.w;
            }
            *(float4*)&s_part[kq][0][colb] = a0;
            *(float4*)&s_part[kq][1][colb] = a1;
            *(float4*)&s_part[kq][2][colb] = a2;
            *(float4*)&s_part[kq][3][colb] = a3;
            __syncthreads();

            float b1v = B1[tid], w2v = W2[tid];
            float h0 = gelu_exact(s_part[0][0][tid] + s_part[1][0][tid] + s_part[2][0][tid] + s_part[3][0][tid] + b1v) * w2v;
            float h1 = gelu_exact(s_part[0][1][tid] + s_part[1][1][tid] + s_part[2][1][tid] + s_part[3][1][tid] + b1v) * w2v;
            float h2 = gelu_exact(s_part[0][2][tid] + s_part[1][2][tid] + s_part[2][2][tid] + s_part[3][2][tid] + b1v) * w2v;
            float h3 = gelu_exact(s_part[0][3][tid] + s_part[1][3][tid] + s_part[2][3][tid] + s_part[3][3][tid] + b1v) * w2v;
            #pragma unroll
            for (int off = 16; off > 0; off >>= 1) {
                h0 += __shfl_down_sync(0xffffffffu, h0, off);
                h1 += __shfl_down_sync(0xffffffffu, h1, off);
                h2 += __shfl_down_sync(0xffffffffu, h2, off);
                h3 += __shfl_down_sync(0xffffffffu, h3, off);
            }
            if (lane == 0) { red[0][w] = h0; red[1][w] = h1; red[2][w] = h2; red[3][w] = h3; }
            __syncthreads();
            if (tid < cnt) {
                float s = red[tid][0] + red[tid][1] + red[tid][2] + red[tid][3]
                        + red[tid][4] + red[tid][5] + red[tid][6] + red[tid][7];
                gateV[g][j0 + tid] = sigmoidf_(s + b2);
            }
            __syncthreads();
        }
    }

    // sparse edge lists + walk init
    if (tid == 0) {
        for (int q = 0; q < nJob[0]; q++) {
            int t = jobT[0][q];
            int src = e_src[t]; src = min(max(src, 0), Ss - 1);
            int tv  = e_tv[t];  tv  = min(max(tv, 0), Vv - 1);
            mS[q] = src; mT[q] = tv; mW[q] = gateV[0][q];
        }
        for (int q = 0; q < nJob[1]; q++) {
            int t = jobT[1][q];
            int src = e_src[t]; src = min(max(src, 0), Ss - 1);
            int ts  = e_ts[t];  ts  = min(max(ts, 0), Ss - 1);
            sS[q] = src; sT[q] = ts; sW[q] = gateV[1][q];
        }
        int q = e_q; q = min(max(q, 0), Ss - 1);
        float qv = (float)e_qv;
        walk[0][q] = qv;
        wsum[q]    = qv;
        wsI[0] = q; wsW[0] = qv;
        s_nws = 1;
    }
    __syncthreads();

    int cur = 0;
    for (int it = 0; it < 3; it++) {
        for (int i = tid; i < Ss; i += 256) walk[cur ^ 1][i] = 0.f;
        __syncthreads();
        if (tid == 0) {
            int ns = nJob[1], nws = s_nws;
            for (int e = 0; e < ns; e++) {
                float v = walk[cur][sS[e]];
                if (v != 0.f) {
                    float c = v * sW[e];
                    walk[cur ^ 1][sT[e]] += c;
                    wsum[sT[e]] += c;
                    wsI[nws] = sT[e]; wsW[nws] = c; nws++;
                }
            }
            s_nws = nws;
        }
        __syncthreads();
        cur ^= 1;
    }

    if (tid == 0) {
        int na = 0;
        for (int e = 0; e < nJob[0]; e++) {
            float v = wsum[mS[e]];
            if (v != 0.f) { avI[na] = mT[e]; avW[na] = v * mW[e]; na++; }
        }
        s_nav = na;
    }
    __syncthreads();

    // gather graph_state
    const int d = tid;              // 256 threads == Dd
    const int nws = s_nws, nav = s_nav;
    float ss = 0.f;
    for (int p = 0; p < nws; p++) ss += wsW[p] * symbol_emb[wsI[p] * Dd + d];
    float vv = 0.f;
    for (int p = 0; p < nav; p++) vv += avW[p] * value_emb[avI[p] * Dd + d];
    g_gs[b * (2 * Dd) + d]      = ss;
    g_gs[b * (2 * Dd) + Dd + d] = vv;
}

// ---------------------------------------------------------------------------
// K2: hidden partials, split-K=8. grid (2 coltiles, 4 rowtiles, 16 = z*8+ks).
// ---------------------------------------------------------------------------
__global__ void __launch_bounds__(256)
k_hidden(const float* __restrict__ Wo1, const float* __restrict__ Wf1)
{
    const int zks = blockIdx.z;
    const int z = zks >> 3, ks = zks & 7;
    const float* W1 = z ? Wf1 : Wo1;
    const int rowt = blockIdx.y, colt = blockIdx.x;

    const int tid = threadIdx.x;
    const int lane = tid & 31, rr = tid >> 5;

    __shared__ float gsS[16][64];
    for (int i = tid; i < 1024; i += 256) {
        int r = i >> 6, kk = i & 63;
        gsS[r][kk] = g_gs[(rowt * 16 + r) * 512 + ks * 64 + kk];
    }
    __syncthreads();

    const int col = colt * 128 + lane * 4;
    const float* Wp = W1 + (ks * 64) * Dd + col;
    float4 a0 = {0,0,0,0}, a1 = {0,0,0,0};
    #pragma unroll 8
    for (int kk = 0; kk < 64; kk++) {
        float4 wv = *(const float4*)(Wp + kk * Dd);
        float x0 = gsS[rr][kk], x1 = gsS[rr + 8][kk];
        a0.x += x0*wv.x; a0.y += x0*wv.y; a0.z += x0*wv.z; a0.w += x0*wv.w;
        a1.x += x1*wv.x; a1.y += x1*wv.y; a1.z += x1*wv.z; a1.w += x1*wv.w;
    }
    const int base = ((ks * 2 + z) * Bsz) * Dd;
    const int r0 = rowt * 16 + rr;
    *(float4*)&g_hp[base + r0 * Dd + col]       = a0;
    *(float4*)&g_hp[base + (r0 + 8) * Dd + col] = a1;
}

// ---------------------------------------------------------------------------
// K3: reconstruct h chunk (sum partials + b1, gelu) then split-K=4 GEMM with
// atomicAdd into bias-initialized d_out. grid (4, 4, 8 = z*4+ks).
// ---------------------------------------------------------------------------
__global__ void __launch_bounds__(256)
k_out(const float* __restrict__ Wo2, const float* __restrict__ Wf2,
      const float* __restrict__ bo1, const float* __restrict__ bf1,
      float* __restrict__ out)
{
    const int z4 = blockIdx.z;
    const int z = z4 >> 2, ks = z4 & 3;
    const int OW = z ? Dd : Vv;
    const int colt = blockIdx.x;
    if (colt * 128 >= OW) return;
    const float* W2 = z ? Wf2 : Wo2;
    const float* B1 = z ? bf1 : bo1;
    const int rowt = blockIdx.y;

    const int tid = threadIdx.x;
    const int lane = tid & 31, rr = tid >> 5;

    __shared__ float hS[16][64];
    for (int i = tid; i < 1024; i += 256) {
        int r = i >> 6, kk = i & 63;
        int c = ks * 64 + kk;
        int row = rowt * 16 + r;
        float s = 0.f;
        #pragma unroll
        for (int ks2 = 0; ks2 < 8; ks2++)
            s += g_hp[((ks2 * 2 + z) * Bsz + row) * Dd + c];
        hS[r][kk] = gelu_exact(s + B1[c]);
    }
    __syncthreads();

    const int col = colt * 128 + lane * 4;
    const float* Wp = W2 + (ks * 64) * OW + col;
    float4 a0 = {0,0,0,0}, a1 = {0,0,0,0};
    #pragma unroll 8
    for (int kk = 0; kk < 64; kk++) {
        float4 wv = *(const float4*)(Wp + kk * OW);
        float x0 = hS[rr][kk], x1 = hS[rr + 8][kk];
        a0.x += x0*wv.x; a0.y += x0*wv.y; a0.z += x0*wv.z; a0.w += x0*wv.w;
        a1.x += x1*wv.x; a1.y += x1*wv.y; a1.z += x1*wv.z; a1.w += x1*wv.w;
    }
    float* ob = z ? (out + Bsz * Vv) : out;
    const int r0 = rowt * 16 + rr;
    float* p0 = ob + r0 * OW + col;
    float* p1 = ob + (r0 + 8) * OW + col;
    atomicAdd(p0 + 0, a0.x); atomicAdd(p0 + 1, a0.y);
    atomicAdd(p0 + 2, a0.z); atomicAdd(p0 + 3, a0.w);
    atomicAdd(p1 + 0, a1.x); atomicAdd(p1 + 1, a1.y);
    atomicAdd(p1 + 2, a1.z); atomicAdd(p1 + 3, a1.w);
}

// ---------------------------------------------------------------------------
extern "C" void kernel_launch(void* const* d_in, const int* in_sizes, int n_in,
                              void* d_out, int out_size)
{
    const int*   marker     = (const int*)d_in[0];
    const int*   srcI       = (const int*)d_in[1];
    const int*   sv         = (const int*)d_in[2];
    const int*   tsymI      = (const int*)d_in[3];
    const int*   tsv        = (const int*)d_in[4];
    const int*   tvalI      = (const int*)d_in[5];
    const int*   tvv        = (const int*)d_in[6];
    const int*   qI         = (const int*)d_in[7];
    const int*   qV         = (const int*)d_in[8];
    const float* evidence   = (const float*)d_in[9];
    const float* symbol_emb = (const float*)d_in[10];
    const float* value_emb  = (const float*)d_in[11];
    const float* Wmg1 = (const float*)d_in[12]; const float* bmg1 = (const float*)d_in[13];
    const float* Wmg2 = (const float*)d_in[14]; const float* bmg2 = (const float*)d_in[15];
    const float* Wsg1 = (const float*)d_in[16]; const float* bsg1 = (const float*)d_in[17];
    const float* Wsg2 = (const float*)d_in[18]; const float* bsg2 = (const float*)d_in[19];
    const float* Wf1  = (const float*)d_in[20]; const float* bf1  = (const float*)d_in[21];
    const float* Wf2  = (const float*)d_in[22]; const float* bf2  = (const float*)d_in[23];
    const float* Wo1  = (const float*)d_in[24]; const float* bo1  = (const float*)d_in[25];
    const float* Wo2  = (const float*)d_in[26]; const float* bo2  = (const float*)d_in[27];
    float* out = (float*)d_out;

    k_gw<<<Bsz, 256>>>(marker, srcI, sv, tsymI, tsv, tvalI, tvv, qI, qV,
                       evidence, symbol_emb, value_emb,
                       Wmg1, bmg1, Wmg2, bmg2, Wsg1, bsg1, Wsg2, bsg2,
                       bo2, bf2, out);
    k_hidden<<<dim3(2, 4, 16), 256>>>(Wo1, Wf1);
    k_out<<<dim3(4, 4, 8), 256>>>(Wo2, Wf2, bo1, bf1, out);
}

// round 8
// speedup vs baseline: 2.3281x; 1.1547x over previous
#include <cuda_runtime.h>
#include <math.h>

#define Bsz 64
#define Tn  12
#define Dd  256
#define Vv  512
#define Ss  512
#define BT  768
#define NB  128   // grid size; all CTAs co-resident (128 <= 148 SMs, 1 CTA/SM)

// scratch (no allocations allowed)
__device__ float g_gs[Bsz * 2 * Dd];                   // graph_state [64, 512]
__device__ __align__(16) float g_hp[8 * 2 * Bsz * Dd]; // hidden partials [ks][z][64][256]
__device__ unsigned g_bar = 0;                          // monotone barrier ticket

__device__ __forceinline__ float gelu_exact(float x) {
    return 0.5f * x * (1.0f + erff(x * 0.70710678118654752440f));
}
__device__ __forceinline__ float sigmoidf_(float x) {
    return 1.0f / (1.0f + expf(-x));
}

// grid-wide barrier: monotone ticket, no reset between graph replays.
__device__ __forceinline__ void grid_sync() {
    __syncthreads();
    if (threadIdx.x == 0) {
        __threadfence();
        unsigned ticket = atomicAdd(&g_bar, 1u);
        unsigned target = (ticket / NB + 1u) * NB;   // end of this barrier's epoch
        while ((int)(*(volatile unsigned*)&g_bar - target) < 0) { }
    }
    __syncthreads();
}

// ---------------------------------------------------------------------------
__global__ void __launch_bounds__(256)
k_all(const int* __restrict__ marker, const int* __restrict__ srcI,
      const int* __restrict__ sv,
      const int* __restrict__ tsymI, const int* __restrict__ tsv,
      const int* __restrict__ tvalI, const int* __restrict__ tvv,
      const int* __restrict__ qI, const int* __restrict__ qV,
      const float* __restrict__ evidence,
      const float* __restrict__ symbol_emb, const float* __restrict__ value_emb,
      const float* __restrict__ Wmg1, const float* __restrict__ bmg1,
      const float* __restrict__ Wmg2, const float* __restrict__ bmg2,
      const float* __restrict__ Wsg1, const float* __restrict__ bsg1,
      const float* __restrict__ Wsg2, const float* __restrict__ bsg2,
      const float* __restrict__ Wf1,  const float* __restrict__ bf1,
      const float* __restrict__ Wf2,  const float* __restrict__ bf2,
      const float* __restrict__ Wo1,  const float* __restrict__ bo1,
      const float* __restrict__ Wo2,  const float* __restrict__ bo2,
      float* __restrict__ out)
{
    const int bx  = blockIdx.x;
    const int tid = threadIdx.x;
    const int lane = tid & 31, w = tid >> 5;

    // ---- shared memory (phase 1 is the high-water mark; later phases reuse) ----
    __shared__ int   e_m[Tn], e_src[Tn], e_sv[Tn], e_ts[Tn], e_tsv[Tn], e_tv[Tn], e_tvv[Tn];
    __shared__ int   e_q, e_qv;
    __shared__ int   jobT[2][Tn];
    __shared__ int   nJob[2];
    __shared__ float gateV[2][Tn];
    __shared__ __align__(16) float xs[4][Dd];
    __shared__ __align__(16) float s_part[4][4][Dd];   // [kq][job][col]  (16KB)
    __shared__ float red[4][8];
    __shared__ float walk[2][Ss];
    __shared__ float wsum[Ss];
    __shared__ int   wsI[64]; __shared__ float wsW[64];
    __shared__ int   avI[16]; __shared__ float avW[16];
    __shared__ int   s_nws, s_nav;
    __shared__ int   mS[Tn], mT[Tn]; __shared__ float mW[Tn];
    __shared__ int   sS[Tn], sT[Tn]; __shared__ float sW[Tn];

    // ======================= PHASE 1 =======================
    if (bx >= Bsz) {
        // bias-init output chunk for batch (bx-64)
        const int b = bx - Bsz;
        #pragma unroll
        for (int j = tid; j < BT; j += 256) {
            int i = b * BT + j;
            out[i] = (i < Bsz * Vv) ? bo2[i & (Vv - 1)] : bf2[i & (Dd - 1)];
        }
    } else {
        const int b = bx;
        for (int i = tid; i < Ss; i += 256) { walk[0][i] = 0.f; wsum[i] = 0.f; }
        if (tid < Tn) {
            int idx = b * Tn + tid;
            e_m[tid]   = marker[idx];
            e_src[tid] = srcI[idx];
            e_sv[tid]  = sv[idx];
            e_ts[tid]  = tsymI[idx];
            e_tsv[tid] = tsv[idx];
            e_tv[tid]  = tvalI[idx];
            e_tvv[tid] = tvv[idx];
        }
        if (tid == Tn) { e_q = qI[b]; e_qv = qV[b]; }
        __syncthreads();

        if (tid == 0) {
            int nm = 0, ns = 0;
            #pragma unroll
            for (int t = 0; t < Tn; t++) {
                int m = e_m[t];
                bool svv = e_sv[t] > 0;
                if (((m == 0) || (m == 1)) && svv && e_tvv[t] > 0) jobT[0][nm++] = t;
                if (m == 2 && svv && e_tsv[t] > 0)                 jobT[1][ns++] = t;
            }
            nJob[0] = nm; nJob[1] = ns;
        }
        __syncthreads();

        // gate MLPs: 4 jobs per pass, k-split (4) x col-split (2) across 8 warps
        const int cg = w & 1, kq = w >> 1;
        const int colb = cg * 128 + lane * 4;

        for (int g = 0; g < 2; g++) {
            const float* W1 = g ? Wsg1 : Wmg1;
            const float* B1 = g ? bsg1 : bmg1;
            const float* W2 = g ? Wsg2 : Wmg2;
            const float  b2 = g ? bsg2[0] : bmg2[0];
            const int nj = nJob[g];

            for (int j0 = 0; j0 < nj; j0 += 4) {
                int cnt = nj - j0; if (cnt > 4) cnt = 4;
                #pragma unroll
                for (int q = 0; q < 4; q++) {
                    int t = jobT[g][j0 + (q < cnt ? q : 0)];
                    xs[q][tid] = evidence[(b * Tn + t) * Dd + tid];
                }
                __syncthreads();

                float4 a0 = {0,0,0,0}, a1 = {0,0,0,0}, a2 = {0,0,0,0}, a3 = {0,0,0,0};
                const float* Wp = W1 + (kq * 64) * Dd + colb;
                #pragma unroll 8
                for (int kk = 0; kk < 64; kk++) {
                    float4 wv = *(const float4*)(Wp + kk * Dd);
                    int k = kq * 64 + kk;
                    float x0 = xs[0][k], x1 = xs[1][k], x2 = xs[2][k], x3 = xs[3][k];
                    a0.x += x0*wv.x; a0.y += x0*wv.y; a0.z += x0*wv.z; a0.w += x0*wv.w;
                    a1.x += x1*wv.x; a1.y += x1*wv.y; a1.z += x1*wv.z; a1.w += x1*wv.w;
                    a2.x += x2*wv.x; a2.y += x2*wv.y; a2.z += x2*wv.z; a2.w += x2*wv.w;
                    a3.x += x3*wv.x; a3.y += x3*wv.y; a3.z += x3*wv.z; a3.w += x3*wv.w;
                }
                *(float4*)&s_part[kq][0][colb] = a0;
                *(float4*)&s_part[kq][1][colb] = a1;
                *(float4*)&s_part[kq][2][colb] = a2;
                *(float4*)&s_part[kq][3][colb] = a3;
                __syncthreads();

                float b1v = B1[tid], w2v = W2[tid];
                float h0 = gelu_exact(s_part[0][0][tid] + s_part[1][0][tid] + s_part[2][0][tid] + s_part[3][0][tid] + b1v) * w2v;
                float h1 = gelu_exact(s_part[0][1][tid] + s_part[1][1][tid] + s_part[2][1][tid] + s_part[3][1][tid] + b1v) * w2v;
                float h2 = gelu_exact(s_part[0][2][tid] + s_part[1][2][tid] + s_part[2][2][tid] + s_part[3][2][tid] + b1v) * w2v;
                float h3 = gelu_exact(s_part[0][3][tid] + s_part[1][3][tid] + s_part[2][3][tid] + s_part[3][3][tid] + b1v) * w2v;
                #pragma unroll
                for (int off = 16; off > 0; off >>= 1) {
                    h0 += __shfl_down_sync(0xffffffffu, h0, off);
                    h1 += __shfl_down_sync(0xffffffffu, h1, off);
                    h2 += __shfl_down_sync(0xffffffffu, h2, off);
                    h3 += __shfl_down_sync(0xffffffffu, h3, off);
                }
                if (lane == 0) { red[0][w] = h0; red[1][w] = h1; red[2][w] = h2; red[3][w] = h3; }
                __syncthreads();
                if (tid < cnt) {
                    float s = red[tid][0] + red[tid][1] + red[tid][2] + red[tid][3]
                            + red[tid][4] + red[tid][5] + red[tid][6] + red[tid][7];
                    gateV[g][j0 + tid] = sigmoidf_(s + b2);
                }
                __syncthreads();
            }
        }

        // sparse edge lists + walk init
        if (tid == 0) {
            for (int q = 0; q < nJob[0]; q++) {
                int t = jobT[0][q];
                int src = e_src[t]; src = min(max(src, 0), Ss - 1);
                int tv  = e_tv[t];  tv  = min(max(tv, 0), Vv - 1);
                mS[q] = src; mT[q] = tv; mW[q] = gateV[0][q];
            }
            for (int q = 0; q < nJob[1]; q++) {
                int t = jobT[1][q];
                int src = e_src[t]; src = min(max(src, 0), Ss - 1);
                int ts  = e_ts[t];  ts  = min(max(ts, 0), Ss - 1);
                sS[q] = src; sT[q] = ts; sW[q] = gateV[1][q];
            }
            int q = e_q; q = min(max(q, 0), Ss - 1);
            float qv = (float)e_qv;
            walk[0][q] = qv;
            wsum[q]    = qv;
            wsI[0] = q; wsW[0] = qv;
            s_nws = 1;
        }
        __syncthreads();

        int cur = 0;
        for (int it = 0; it < 3; it++) {
            for (int i = tid; i < Ss; i += 256) walk[cur ^ 1][i] = 0.f;
            __syncthreads();
            if (tid == 0) {
                int ns = nJob[1], nws = s_nws;
                for (int e = 0; e < ns; e++) {
                    float v = walk[cur][sS[e]];
                    if (v != 0.f) {
                        float c = v * sW[e];
                        walk[cur ^ 1][sT[e]] += c;
                        wsum[sT[e]] += c;
                        wsI[nws] = sT[e]; wsW[nws] = c; nws++;
                    }
                }
                s_nws = nws;
            }
            __syncthreads();
            cur ^= 1;
        }

        if (tid == 0) {
            int na = 0;
            for (int e = 0; e < nJob[0]; e++) {
                float v = wsum[mS[e]];
                if (v != 0.f) { avI[na] = mT[e]; avW[na] = v * mW[e]; na++; }
            }
            s_nav = na;
        }
        __syncthreads();

        const int d = tid;
        const int nws = s_nws, nav = s_nav;
        float ss = 0.f;
        for (int p = 0; p < nws; p++) ss += wsW[p] * symbol_emb[wsI[p] * Dd + d];
        float vv = 0.f;
        for (int p = 0; p < nav; p++) vv += avW[p] * value_emb[avI[p] * Dd + d];
        g_gs[b * (2 * Dd) + d]      = ss;
        g_gs[b * (2 * Dd) + Dd + d] = vv;
    }

    grid_sync();

    // ======================= PHASE 2: hidden partials, split-K=8 =======================
    // 128 tiles: x = zks*8 + rowt*2 + colt
    {
        const int colt = bx & 1, rowt = (bx >> 1) & 3, zks = bx >> 3;
        const int z = zks >> 3, ks = zks & 7;
        const float* W1 = z ? Wf1 : Wo1;
        const int rr = tid >> 5;

        float (*gsS)[64] = (float(*)[64])walk;  // reuse smem
        for (int i = tid; i < 1024; i += 256) {
            int r = i >> 6, kk = i & 63;
            gsS[r][kk] = __ldcg(&g_gs[(rowt * 16 + r) * 512 + ks * 64 + kk]);
        }
        __syncthreads();

        const int col = colt * 128 + lane * 4;
        const float* Wp = W1 + (ks * 64) * Dd + col;
        float4 a0 = {0,0,0,0}, a1 = {0,0,0,0};
        #pragma unroll 8
        for (int kk = 0; kk < 64; kk++) {
            float4 wv = *(const float4*)(Wp + kk * Dd);
            float x0 = gsS[rr][kk], x1 = gsS[rr + 8][kk];
            a0.x += x0*wv.x; a0.y += x0*wv.y; a0.z += x0*wv.z; a0.w += x0*wv.w;
            a1.x += x1*wv.x; a1.y += x1*wv.y; a1.z += x1*wv.z; a1.w += x1*wv.w;
        }
        const int base = ((ks * 2 + z) * Bsz) * Dd;
        const int r0 = rowt * 16 + rr;
        *(float4*)&g_hp[base + r0 * Dd + col]       = a0;
        *(float4*)&g_hp[base + (r0 + 8) * Dd + col] = a1;
    }

    grid_sync();

    // ======================= PHASE 3: output, split-K=4 + atomics ======================
    // x = z4*16 + rowt*4 + colt ; z4 = z*4+ks
    {
        const int colt = bx & 3, rowt = (bx >> 2) & 3, z4 = bx >> 4;
        const int z = z4 >> 2, ks = z4 & 3;
        const int OW = z ? Dd : Vv;
        if (colt * 128 < OW) {
            const float* W2 = z ? Wf2 : Wo2;
            const float* B1 = z ? bf1 : bo1;
            const int rr = tid >> 5;

            float (*hS)[64] = (float(*)[64])walk;  // reuse smem
            for (int i = tid; i < 1024; i += 256) {
                int r = i >> 6, kk = i & 63;
                int c = ks * 64 + kk;
                int row = rowt * 16 + r;
                float s = 0.f;
                #pragma unroll
                for (int ks2 = 0; ks2 < 8; ks2++)
                    s += __ldcg(&g_hp[((ks2 * 2 + z) * Bsz + row) * Dd + c]);
                hS[r][kk] = gelu_exact(s + B1[c]);
            }
            __syncthreads();

            const int col = colt * 128 + lane * 4;
            const float* Wp = W2 + (ks * 64) * OW + col;
            float4 a0 = {0,0,0,0}, a1 = {0,0,0,0};
            #pragma unroll 8
            for (int kk = 0; kk < 64; kk++) {
                float4 wv = *(const float4*)(Wp + kk * OW);
                float x0 = hS[rr][kk], x1 = hS[rr + 8][kk];
                a0.x += x0*wv.x; a0.y += x0*wv.y; a0.z += x0*wv.z; a0.w += x0*wv.w;
                a1.x += x1*wv.x; a1.y += x1*wv.y; a1.z += x1*wv.z; a1.w += x1*wv.w;
            }
            float* ob = z ? (out + Bsz * Vv) : out;
            const int r0 = rowt * 16 + rr;
            float* p0 = ob + r0 * OW + col;
            float* p1 = ob + (r0 + 8) * OW + col;
            atomicAdd(p0 + 0, a0.x); atomicAdd(p0 + 1, a0.y);
            atomicAdd(p0 + 2, a0.z); atomicAdd(p0 + 3, a0.w);
            atomicAdd(p1 + 0, a1.x); atomicAdd(p1 + 1, a1.y);
            atomicAdd(p1 + 2, a1.z); atomicAdd(p1 + 3, a1.w);
        }
    }
}

// ---------------------------------------------------------------------------
extern "C" void kernel_launch(void* const* d_in, const int* in_sizes, int n_in,
                              void* d_out, int out_size)
{
    const int*   marker     = (const int*)d_in[0];
    const int*   srcI       = (const int*)d_in[1];
    const int*   sv         = (const int*)d_in[2];
    const int*   tsymI      = (const int*)d_in[3];
    const int*   tsv        = (const int*)d_in[4];
    const int*   tvalI      = (const int*)d_in[5];
    const int*   tvv        = (const int*)d_in[6];
    const int*   qI         = (const int*)d_in[7];
    const int*   qV         = (const int*)d_in[8];
    const float* evidence   = (const float*)d_in[9];
    const float* symbol_emb = (const float*)d_in[10];
    const float* value_emb  = (const float*)d_in[11];
    const float* Wmg1 = (const float*)d_in[12]; const float* bmg1 = (const float*)d_in[13];
    const float* Wmg2 = (const float*)d_in[14]; const float* bmg2 = (const float*)d_in[15];
    const float* Wsg1 = (const float*)d_in[16]; const float* bsg1 = (const float*)d_in[17];
    const float* Wsg2 = (const float*)d_in[18]; const float* bsg2 = (const float*)d_in[19];
    const float* Wf1  = (const float*)d_in[20]; const float* bf1  = (const float*)d_in[21];
    const float* Wf2  = (const float*)d_in[22]; const float* bf2  = (const float*)d_in[23];
    const float* Wo1  = (const float*)d_in[24]; const float* bo1  = (const float*)d_in[25];
    const float* Wo2  = (const float*)d_in[26]; const float* bo2  = (const float*)d_in[27];
    float* out = (float*)d_out;

    k_all<<<NB, 256>>>(marker, srcI, sv, tsymI, tsv, tvalI, tvv, qI, qV,
                       evidence, symbol_emb, value_emb,
                       Wmg1, bmg1, Wmg2, bmg2, Wsg1, bsg1, Wsg2, bsg2,
                       Wf1, bf1, Wf2, bf2, Wo1, bo1, Wo2, bo2, out);
}